// round 15
// baseline (speedup 1.0000x reference)
#include <cuda_runtime.h>
#include <cuda_bf16.h>
#include <math.h>
#include <stdint.h>

#define B_   4
#define CIN  256
#define CP   128
#define NS   4096

__device__ float g_g[B_*CP*NS];
__device__ float g_z[B_*CIN*NS];
__device__ float g_bnsum[CIN];
__device__ float g_bnsq[CIN];
__device__ float g_mean[CIN];
__device__ float g_invstd[CIN];
__device__ __nv_bfloat16 g_xh[B_*CIN*NS], g_xl[B_*CIN*NS];
__device__ __nv_bfloat16 g_Wth[CP*CIN], g_Wtl[CP*CIN];
__device__ __nv_bfloat16 g_Wph[CP*CIN], g_Wpl[CP*CIN];
__device__ __nv_bfloat16 g_Wgh[CP*CIN], g_Wgl[CP*CIN];
__device__ __nv_bfloat16 g_Wzh[CIN*CP], g_Wzl[CIN*CP];
__device__ __nv_bfloat16 g_th[B_*CP*NS], g_tl[B_*CP*NS];
__device__ __nv_bfloat16 g_ph[B_*CP*NS], g_pl[B_*CP*NS];
__device__ __nv_bfloat16 g_gh[B_*CP*NS], g_gl[B_*CP*NS];
__device__ __nv_bfloat16 g_yh[B_*CP*NS], g_yl[B_*CP*NS];
__device__ __nv_bfloat16 g_Eh[(size_t)B_*NS*NS], g_El[(size_t)B_*NS*NS];

// ---------------- helpers ----------------
__device__ __forceinline__ uint32_t smem_u32(const void* p) {
    uint32_t a;
    asm("{ .reg .u64 t; cvta.to.shared.u64 t, %1; cvt.u32.u64 %0, t; }" : "=r"(a) : "l"(p));
    return a;
}
#define CP16(dst, src) asm volatile("cp.async.cg.shared.global [%0], [%1], 16;" :: "r"(dst), "l"(src))
#define CPCOMMIT() asm volatile("cp.async.commit_group;" ::: "memory")
#define CPWAIT0() asm volatile("cp.async.wait_group 0;" ::: "memory")
#define CPWAIT1() asm volatile("cp.async.wait_group 1;" ::: "memory")

__device__ __forceinline__ void ldm_x4_t(uint32_t* r, uint32_t addr) {
    asm volatile("ldmatrix.sync.aligned.m8n8.x4.trans.shared.b16 {%0,%1,%2,%3}, [%4];"
        : "=r"(r[0]), "=r"(r[1]), "=r"(r[2]), "=r"(r[3]) : "r"(addr));
}
__device__ __forceinline__ void ldm_x4(uint32_t* r, uint32_t addr) {
    asm volatile("ldmatrix.sync.aligned.m8n8.x4.shared.b16 {%0,%1,%2,%3}, [%4];"
        : "=r"(r[0]), "=r"(r[1]), "=r"(r[2]), "=r"(r[3]) : "r"(addr));
}
__device__ __forceinline__ void mma_bf16(float* c, const uint32_t* a, const uint32_t* b) {
    asm volatile("mma.sync.aligned.m16n8k16.row.col.f32.bf16.bf16.f32 "
        "{%0,%1,%2,%3}, {%4,%5,%6,%7}, {%8,%9}, {%0,%1,%2,%3};"
        : "+f"(c[0]), "+f"(c[1]), "+f"(c[2]), "+f"(c[3])
        : "r"(a[0]), "r"(a[1]), "r"(a[2]), "r"(a[3]), "r"(b[0]), "r"(b[1]));
}
__device__ __forceinline__ void split2(float a, float b, uint32_t& h, uint32_t& l) {
    __nv_bfloat16 ha = __float2bfloat16(a), hb = __float2bfloat16(b);
    h = (uint32_t)__bfloat16_as_ushort(ha) | ((uint32_t)__bfloat16_as_ushort(hb) << 16);
    __nv_bfloat16 la = __float2bfloat16(a - __bfloat162float(ha));
    __nv_bfloat16 lb = __float2bfloat16(b - __bfloat162float(hb));
    l = (uint32_t)__bfloat16_as_ushort(la) | ((uint32_t)__bfloat16_as_ushort(lb) << 16);
}

// ============================================================
// small kernels
// ============================================================
__global__ __launch_bounds__(256) void zero_bn_kernel()
{
    if (threadIdx.x < CIN) { g_bnsum[threadIdx.x] = 0.f; g_bnsq[threadIdx.x] = 0.f; }
}
__global__ __launch_bounds__(256) void bn_finalize_kernel()
{
    int c = threadIdx.x;
    if (c < CIN) {
        const float inv_n = 1.0f / (float)(B_*NS);
        float mean = g_bnsum[c] * inv_n;
        float var  = g_bnsq[c] * inv_n - mean*mean;
        g_mean[c] = mean;
        g_invstd[c] = rsqrtf(var + 1e-5f);
    }
}
__global__ __launch_bounds__(256) void split_kernel(
    const float* __restrict__ src, __nv_bfloat16* __restrict__ h,
    __nv_bfloat16* __restrict__ l, int n)
{
    int i = blockIdx.x*256 + threadIdx.x;
    if (i >= n) return;
    float v = src[i];
    __nv_bfloat16 hb = __float2bfloat16(v);
    h[i] = hb;
    l[i] = __float2bfloat16(v - __bfloat162float(hb));
}
__global__ __launch_bounds__(256) void split2_kernel(
    const float* __restrict__ s1, __nv_bfloat16* __restrict__ h1, __nv_bfloat16* __restrict__ l1,
    const float* __restrict__ s2, __nv_bfloat16* __restrict__ h2, __nv_bfloat16* __restrict__ l2,
    int n)
{
    int i = blockIdx.x*256 + threadIdx.x;
    if (i >= n) return;
    float v = s1[i];
    __nv_bfloat16 hb = __float2bfloat16(v);
    h1[i] = hb; l1[i] = __float2bfloat16(v - __bfloat162float(hb));
    v = s2[i];
    hb = __float2bfloat16(v);
    h2[i] = hb; l2[i] = __float2bfloat16(v - __bfloat162float(hb));
}

// ============================================================
// shared GEMM machinery: 128x128 CTA tile, 64-k chunks, templated stages
// ============================================================
#define ATS 72
#define ATB 18432u
#define BTS 136
#define BTB 17408u
#define ABUF (2u*ATB + 2u*BTB)
#define G_SMEM  (3u*ABUF)
#define G_SMEM2 (2u*ABUF)

__device__ __forceinline__ void stage_g(uint32_t buf,
    const __nv_bfloat16* Ah, const __nv_bfloat16* Al,
    const __nv_bfloat16* Bh, const __nv_bfloat16* Bl,
    int kc, int m0, int n0, int K, int tid)
{
    #pragma unroll
    for (int i = 0; i < 2; i++) {
        int idx = tid + i*512, row = idx>>3, ch = idx&7;
        uint32_t d = (uint32_t)(row*(ATS*2) + ch*16);
        size_t so = (size_t)(m0+row)*K + kc*64 + ch*8;
        CP16(buf + d,       Ah + so);
        CP16(buf + ATB + d, Al + so);
    }
    #pragma unroll
    for (int i = 0; i < 2; i++) {
        int idx = tid + i*512, row = idx>>4, ch = idx&15;
        uint32_t d = (uint32_t)(row*(BTS*2) + ch*16);
        size_t so = (size_t)(kc*64+row)*NS + n0 + ch*8;
        CP16(buf + 2u*ATB + d,       Bh + so);
        CP16(buf + 2u*ATB + BTB + d, Bl + so);
    }
}

template<int NST>
__device__ __forceinline__ void gemm_loop(uint32_t sb,
    const __nv_bfloat16* pAh, const __nv_bfloat16* pAl,
    const __nv_bfloat16* pBh, const __nv_bfloat16* pBl,
    int m0, int n0, int K, int nk, int tid, int wid, int lane,
    float acc[2][4][4])
{
    #pragma unroll
    for (int s = 0; s < NST; s++) {
        if (s < nk) stage_g(sb + (uint32_t)s*ABUF, pAh, pAl, pBh, pBl, s, m0, n0, K, tid);
        CPCOMMIT();
    }
    const int wc = (wid&3)*32, wn = (wid>>2)*32;
    const uint32_t rowAa = (lane&15), colAa = (lane>>4)*8;
    const uint32_t rowB16 = (lane&15), colB8 = (lane>>4)*8;

    int sslot = 0;
    for (int kc = 0; kc < nk; kc++) {
        asm volatile("cp.async.wait_group %0;" :: "n"(NST-1));
        __syncthreads();
        const uint32_t buf = sb + (uint32_t)sslot*ABUF;
        #pragma unroll
        for (int k0 = 0; k0 < 64; k0 += 16) {
            uint32_t ah[2][4], al[2][4], bh[2][4], bl[2][4];
            #pragma unroll
            for (int ct = 0; ct < 2; ct++) {
                uint32_t ao = buf + ((wc + ct*16 + rowAa)*ATS + k0 + colAa)*2;
                ldm_x4(ah[ct], ao);
                ldm_x4(al[ct], ao + ATB);
            }
            #pragma unroll
            for (int j = 0; j < 2; j++) {
                uint32_t bo = buf + 2u*ATB + ((k0+rowB16)*BTS + wn + j*16 + colB8)*2;
                ldm_x4_t(bh[j], bo);
                ldm_x4_t(bl[j], bo + BTB);
            }
            #pragma unroll
            for (int ct = 0; ct < 2; ct++)
                #pragma unroll
                for (int nt = 0; nt < 4; nt++)
                    mma_bf16(acc[ct][nt], ah[ct], &bh[nt>>1][(nt&1)*2]);
            #pragma unroll
            for (int ct = 0; ct < 2; ct++)
                #pragma unroll
                for (int nt = 0; nt < 4; nt++)
                    mma_bf16(acc[ct][nt], ah[ct], &bl[nt>>1][(nt&1)*2]);
            #pragma unroll
            for (int ct = 0; ct < 2; ct++)
                #pragma unroll
                for (int nt = 0; nt < 4; nt++)
                    mma_bf16(acc[ct][nt], al[ct], &bh[nt>>1][(nt&1)*2]);
        }
        __syncthreads();
        if (kc + NST < nk)
            stage_g(buf, pAh, pAl, pBh, pBl, kc+NST, m0, n0, K, tid);
        CPCOMMIT();
        sslot = (sslot == NST-1) ? 0 : sslot + 1;
    }
}

__device__ __forceinline__ void epi_bf(__nv_bfloat16* ch, __nv_bfloat16* cl,
                                       float acc[2][4][4], int m0, int n0, int wid, int lane)
{
    const int wc = (wid&3)*32, wn = (wid>>2)*32;
    const int r0 = lane>>2, cb = (lane&3)*2;
    #pragma unroll
    for (int ct = 0; ct < 2; ct++) {
        const int cg = m0 + wc + ct*16 + r0;
        #pragma unroll
        for (int nt = 0; nt < 4; nt++) {
            const int ng = n0 + wn + nt*8 + cb;
            uint32_t h, l;
            split2(acc[ct][nt][0], acc[ct][nt][1], h, l);
            *(uint32_t*)(ch + (size_t)cg*NS + ng) = h;
            *(uint32_t*)(cl + (size_t)cg*NS + ng) = l;
            split2(acc[ct][nt][2], acc[ct][nt][3], h, l);
            *(uint32_t*)(ch + (size_t)(cg+8)*NS + ng) = h;
            *(uint32_t*)(cl + (size_t)(cg+8)*NS + ng) = l;
        }
    }
}
__device__ __forceinline__ void epi_f32(float* Cout, float acc[2][4][4],
                                        int m0, int n0, int wid, int lane)
{
    const int wc = (wid&3)*32, wn = (wid>>2)*32;
    const int r0 = lane>>2, cb = (lane&3)*2;
    #pragma unroll
    for (int ct = 0; ct < 2; ct++) {
        const int cg = m0 + wc + ct*16 + r0;
        #pragma unroll
        for (int nt = 0; nt < 4; nt++) {
            const int ng = n0 + wn + nt*8 + cb;
            *(float2*)(Cout + (size_t)cg*NS + ng)     = make_float2(acc[ct][nt][0], acc[ct][nt][1]);
            *(float2*)(Cout + (size_t)(cg+8)*NS + ng) = make_float2(acc[ct][nt][2], acc[ct][nt][3]);
        }
    }
}

// ============================================================
// proj: one launch for t/p/g. grid (32, 3, 4), 512 thr, 2 CTA/SM
// ============================================================
__global__ __launch_bounds__(512, 2) void proj_mma()
{
    extern __shared__ char smem[];
    const int b = blockIdx.z, w = blockIdx.y, n0 = blockIdx.x*128;
    const int tid = threadIdx.x, wid = tid>>5, lane = tid&31;
    const uint32_t sb = smem_u32(smem);
    const __nv_bfloat16* Ah = (w == 0) ? g_Wth : (w == 1) ? g_Wph : g_Wgh;
    const __nv_bfloat16* Al = (w == 0) ? g_Wtl : (w == 1) ? g_Wpl : g_Wgl;
    const __nv_bfloat16* Bh = g_xh + (size_t)b*CIN*NS;
    const __nv_bfloat16* Bl = g_xl + (size_t)b*CIN*NS;

    float acc[2][4][4] = {};
    gemm_loop<2>(sb, Ah, Al, Bh, Bl, 0, n0, CIN, CIN/64, tid, wid, lane, acc);

    if (w == 0)      epi_bf(g_th + (size_t)b*CP*NS, g_tl + (size_t)b*CP*NS, acc, 0, n0, wid, lane);
    else if (w == 1) epi_bf(g_ph + (size_t)b*CP*NS, g_pl + (size_t)b*CP*NS, acc, 0, n0, wid, lane);
    else             epi_f32(g_g + (size_t)b*CP*NS, acc, 0, n0, wid, lane);
}

// ============================================================
// apply: y = g'·E. grid (32, 1, 4), 3-stage (grid-limited occupancy)
// ============================================================
__global__ __launch_bounds__(512) void apply_mma()
{
    extern __shared__ char smem[];
    const int b = blockIdx.z, n0 = blockIdx.x*128;
    const int tid = threadIdx.x, wid = tid>>5, lane = tid&31;
    const uint32_t sb = smem_u32(smem);

    float acc[2][4][4] = {};
    gemm_loop<3>(sb, g_gh + (size_t)b*CP*NS, g_gl + (size_t)b*CP*NS,
                 g_Eh + (size_t)b*NS*NS, g_El + (size_t)b*NS*NS,
                 0, n0, NS, NS>>6, tid, wid, lane, acc);
    epi_bf(g_yh + (size_t)b*CP*NS, g_yl + (size_t)b*CP*NS, acc, 0, n0, wid, lane);
}

// ============================================================
// z: z = Wz·y + fused BN partial sums. grid (32, 2, 4), 2 CTA/SM
// ============================================================
__global__ __launch_bounds__(512, 2) void z_mma()
{
    extern __shared__ char smem[];
    __shared__ float s_bn[256];
    const int b = blockIdx.z, m0 = blockIdx.y*128, n0 = blockIdx.x*128;
    const int tid = threadIdx.x, wid = tid>>5, lane = tid&31;
    const uint32_t sb = smem_u32(smem);

    if (tid < 256) s_bn[tid] = 0.f;

    float acc[2][4][4] = {};
    gemm_loop<2>(sb, g_Wzh, g_Wzl, g_yh + (size_t)b*CP*NS, g_yl + (size_t)b*CP*NS,
                 m0, n0, CP, CP>>6, tid, wid, lane, acc);

    __syncthreads();
    const int wc = (wid&3)*32, wn = (wid>>2)*32;
    const int r0 = lane>>2, cb = (lane&3)*2;
    float* Cout = g_z + (size_t)b*CIN*NS;
    #pragma unroll
    for (int ct = 0; ct < 2; ct++) {
        const int lc = wc + ct*16 + r0;
        const int cg = m0 + lc;
        float s0 = 0.f, q0 = 0.f, s1 = 0.f, q1 = 0.f;
        #pragma unroll
        for (int nt = 0; nt < 4; nt++) {
            const int ng = n0 + wn + nt*8 + cb;
            float z0 = acc[ct][nt][0], z1 = acc[ct][nt][1];
            float z2 = acc[ct][nt][2], z3 = acc[ct][nt][3];
            *(float2*)(Cout + (size_t)cg*NS + ng)     = make_float2(z0, z1);
            *(float2*)(Cout + (size_t)(cg+8)*NS + ng) = make_float2(z2, z3);
            s0 += z0 + z1; q0 += z0*z0 + z1*z1;
            s1 += z2 + z3; q1 += z2*z2 + z3*z3;
        }
        #pragma unroll
        for (int sh = 1; sh < 4; sh <<= 1) {
            s0 += __shfl_xor_sync(0xFFFFFFFF, s0, sh);
            q0 += __shfl_xor_sync(0xFFFFFFFF, q0, sh);
            s1 += __shfl_xor_sync(0xFFFFFFFF, s1, sh);
            q1 += __shfl_xor_sync(0xFFFFFFFF, q1, sh);
        }
        if ((lane&3) == 0) {
            atomicAdd(s_bn + lc, s0);        atomicAdd(s_bn + 128 + lc, q0);
            atomicAdd(s_bn + lc + 8, s1);    atomicAdd(s_bn + 128 + lc + 8, q1);
        }
    }
    __syncthreads();
    if (tid < 128) {
        atomicAdd(&g_bnsum[m0 + tid], s_bn[tid]);
        atomicAdd(&g_bnsq[m0 + tid],  s_bn[128 + tid]);
    }
}

// ============================================================
// logits (R10/R14): s = p^T t; E=exp(s) hi/lo SMEM-staged coalesced;
// Linv + gscale fused. grid (32, 4), 512 thr
// ============================================================
#define LTS 136
#define LTB 34816u
#define L_SMEM (6u*LTB)

__device__ __forceinline__ void stage_pt(uint32_t dbase, const __nv_bfloat16* sh,
                                         const __nv_bfloat16* sl, int col0, int tid) {
    #pragma unroll
    for (int i = 0; i < 4; i++) {
        int idx = tid + i*512, row = idx>>4, ch = idx&15;
        uint32_t d = (uint32_t)(row*(LTS*2) + ch*16);
        CP16(dbase + d,       sh + (size_t)row*NS + col0 + ch*8);
        CP16(dbase + LTB + d, sl + (size_t)row*NS + col0 + ch*8);
    }
}

__global__ __launch_bounds__(512) void logits_mma()
{
    extern __shared__ char smem[];
    const int b = blockIdx.y, m0 = blockIdx.x*128;
    const int tid = threadIdx.x, wid = tid>>5, lane = tid&31;
    const uint32_t sb = smem_u32(smem);
    const __nv_bfloat16* th = g_th + (size_t)b*CP*NS;
    const __nv_bfloat16* tl = g_tl + (size_t)b*CP*NS;

    stage_pt(sb, g_ph + (size_t)b*CP*NS, g_pl + (size_t)b*CP*NS, m0, tid);
    stage_pt(sb + 2u*LTB, th, tl, 0, tid);     CPCOMMIT();
    stage_pt(sb + 4u*LTB, th, tl, 128, tid);   CPCOMMIT();

    const int mw = (wid&3)*32, nw = (wid>>2)*32;
    const uint32_t rowA = (lane&7) + ((lane>>4)<<3);
    const uint32_t colA = ((lane>>3)&1)*8;
    const uint32_t rowB16 = (lane&15), colB8 = (lane>>4)*8;
    const int r0 = lane>>2, cb = (lane&3)*2;

    float acc[2][4][4] = {};
    float rs[2][2] = {};

    for (int nc = 0; nc < 32; nc++) {
        if (nc >= 30) { CPWAIT0(); } else { CPWAIT1(); }
        __syncthreads();
        const uint32_t bufB = sb + 2u*LTB + (uint32_t)(nc&1)*(2u*LTB);
        #pragma unroll
        for (int k0 = 0; k0 < 128; k0 += 16) {
            uint32_t ah[2][4], al[2][4], bh[2][4], bl[2][4];
            #pragma unroll
            for (int mt = 0; mt < 2; mt++) {
                uint32_t ao = sb + ((k0+rowA)*LTS + mw + mt*16 + colA)*2;
                ldm_x4_t(ah[mt], ao);
                ldm_x4_t(al[mt], ao + LTB);
            }
            #pragma unroll
            for (int j = 0; j < 2; j++) {
                uint32_t bo = bufB + ((k0+rowB16)*LTS + nw + j*16 + colB8)*2;
                ldm_x4_t(bh[j], bo);
                ldm_x4_t(bl[j], bo + LTB);
            }
            #pragma unroll
            for (int mt = 0; mt < 2; mt++)
                #pragma unroll
                for (int nt = 0; nt < 4; nt++)
                    mma_bf16(acc[mt][nt], ah[mt], &bh[nt>>1][(nt&1)*2]);
            #pragma unroll
            for (int mt = 0; mt < 2; mt++)
                #pragma unroll
                for (int nt = 0; nt < 4; nt++)
                    mma_bf16(acc[mt][nt], ah[mt], &bl[nt>>1][(nt&1)*2]);
            #pragma unroll
            for (int mt = 0; mt < 2; mt++)
                #pragma unroll
                for (int nt = 0; nt < 4; nt++)
                    mma_bf16(acc[mt][nt], al[mt], &bh[nt>>1][(nt&1)*2]);
        }
        __syncthreads();

        #pragma unroll
        for (int mt = 0; mt < 2; mt++) {
            const int lr = mw + mt*16 + r0;
            #pragma unroll
            for (int nt = 0; nt < 4; nt++) {
                float e0 = __expf(acc[mt][nt][0]);
                float e1 = __expf(acc[mt][nt][1]);
                float e2 = __expf(acc[mt][nt][2]);
                float e3 = __expf(acc[mt][nt][3]);
                rs[mt][0] += e0 + e1;
                rs[mt][1] += e2 + e3;
                const int lc = nw + nt*8 + cb;
                uint32_t h, l;
                split2(e0, e1, h, l);
                *(uint32_t*)(smem + (bufB - sb) + (uint32_t)(lr*LTS + lc)*2)       = h;
                *(uint32_t*)(smem + (bufB - sb) + LTB + (uint32_t)(lr*LTS + lc)*2) = l;
                split2(e2, e3, h, l);
                *(uint32_t*)(smem + (bufB - sb) + (uint32_t)((lr+8)*LTS + lc)*2)       = h;
                *(uint32_t*)(smem + (bufB - sb) + LTB + (uint32_t)((lr+8)*LTS + lc)*2) = l;
                acc[mt][nt][0]=acc[mt][nt][1]=acc[mt][nt][2]=acc[mt][nt][3]=0.f;
            }
        }
        __syncthreads();
        {
            const char* sB = smem + (bufB - sb);
            #pragma unroll
            for (int i = 0; i < 4; i++) {
                int idx = tid + i*512, row = idx>>4, ch = idx&15;
                size_t go = ((size_t)b*NS + m0 + row)*NS + nc*128 + ch*8;
                *(uint4*)(g_Eh + go) = *(const uint4*)(sB + (uint32_t)(row*LTS)*2 + ch*16);
                *(uint4*)(g_El + go) = *(const uint4*)(sB + LTB + (uint32_t)(row*LTS)*2 + ch*16);
            }
        }
        __syncthreads();
        if (nc + 2 < 32) {
            stage_pt(bufB, th, tl, (nc+2)*128, tid);
            CPCOMMIT();
        }
    }

    #pragma unroll
    for (int mt = 0; mt < 2; mt++)
        #pragma unroll
        for (int h = 0; h < 2; h++) {
            rs[mt][h] += __shfl_xor_sync(0xFFFFFFFF, rs[mt][h], 1);
            rs[mt][h] += __shfl_xor_sync(0xFFFFFFFF, rs[mt][h], 2);
        }
    __syncthreads();
    float* red = (float*)smem;
    if ((lane&3) == 0) {
        #pragma unroll
        for (int mt = 0; mt < 2; mt++)
            #pragma unroll
            for (int h = 0; h < 2; h++)
                red[(wid>>2)*128 + mw + mt*16 + r0 + h*8] = rs[mt][h];
    }
    __syncthreads();
    float* linv = (float*)(smem + 2048);
    if (tid < 128)
        linv[tid] = 1.0f / (red[tid] + red[128+tid] + red[256+tid] + red[384+tid]);
    __syncthreads();

    {
        const int c = tid >> 2, ms = (tid & 3) * 32;
        const float* gp = g_g + ((size_t)b*CP + c)*NS + m0 + ms;
        __nv_bfloat16* ghp = g_gh + ((size_t)b*CP + c)*NS + m0 + ms;
        __nv_bfloat16* glp = g_gl + ((size_t)b*CP + c)*NS + m0 + ms;
        #pragma unroll
        for (int j = 0; j < 32; j += 4) {
            float4 v = *(const float4*)(gp + j);
            v.x *= linv[ms+j]; v.y *= linv[ms+j+1]; v.z *= linv[ms+j+2]; v.w *= linv[ms+j+3];
            uint32_t h0, l0, h1, l1;
            split2(v.x, v.y, h0, l0);
            split2(v.z, v.w, h1, l1);
            *(uint2*)(ghp + j) = make_uint2(h0, h1);
            *(uint2*)(glp + j) = make_uint2(l0, l1);
        }
    }
}

// ============================================================
// bn_apply: vectorized float4
// ============================================================
__global__ __launch_bounds__(512) void bn_apply_kernel(
    const float* __restrict__ x, const float* __restrict__ gamma,
    const float* __restrict__ beta, float* __restrict__ out)
{
    size_t i4 = ((size_t)blockIdx.x*512 + threadIdx.x) * 4;
    int c = (int)((i4 / NS) % CIN);
    float mean = g_mean[c], invstd = g_invstd[c];
    float ga = gamma[c], be = beta[c];
    float4 zv = *(const float4*)(g_z + i4);
    float4 xv = *(const float4*)(x + i4);
    float4 o;
    o.x = (zv.x - mean)*invstd*ga + be + xv.x;
    o.y = (zv.y - mean)*invstd*ga + be + xv.y;
    o.z = (zv.z - mean)*invstd*ga + be + xv.z;
    o.w = (zv.w - mean)*invstd*ga + be + xv.w;
    *(float4*)(out + i4) = o;
}

// ============================================================
extern "C" void kernel_launch(void* const* d_in, const int* in_sizes, int n_in,
                              void* d_out, int out_size)
{
    const float* x     = (const float*)d_in[0];
    const float* Wt    = (const float*)d_in[1];
    const float* Wp    = (const float*)d_in[2];
    const float* Wg    = (const float*)d_in[3];
    const float* Wz    = (const float*)d_in[4];
    const float* gamma = (const float*)d_in[5];
    const float* beta  = (const float*)d_in[6];
    float* out = (float*)d_out;

    cudaFuncSetAttribute(proj_mma,   cudaFuncAttributeMaxDynamicSharedMemorySize, G_SMEM2);
    cudaFuncSetAttribute(apply_mma,  cudaFuncAttributeMaxDynamicSharedMemorySize, G_SMEM);
    cudaFuncSetAttribute(z_mma,      cudaFuncAttributeMaxDynamicSharedMemorySize, G_SMEM2);
    cudaFuncSetAttribute(logits_mma, cudaFuncAttributeMaxDynamicSharedMemorySize, L_SMEM);

    __nv_bfloat16 *xh, *xl, *Wth, *Wtl, *Wph, *Wpl, *Wgh, *Wgl, *Wzh, *Wzl;
    cudaGetSymbolAddress((void**)&xh, g_xh);   cudaGetSymbolAddress((void**)&xl, g_xl);
    cudaGetSymbolAddress((void**)&Wth, g_Wth); cudaGetSymbolAddress((void**)&Wtl, g_Wtl);
    cudaGetSymbolAddress((void**)&Wph, g_Wph); cudaGetSymbolAddress((void**)&Wpl, g_Wpl);
    cudaGetSymbolAddress((void**)&Wgh, g_Wgh); cudaGetSymbolAddress((void**)&Wgl, g_Wgl);
    cudaGetSymbolAddress((void**)&Wzh, g_Wzh); cudaGetSymbolAddress((void**)&Wzl, g_Wzl);

    zero_bn_kernel<<<1, 256>>>();
    split_kernel <<<(B_*CIN*NS + 255)/256, 256>>>(x, xh, xl, B_*CIN*NS);
    split2_kernel<<<(CP*CIN + 255)/256, 256>>>(Wt, Wth, Wtl, Wp, Wph, Wpl, CP*CIN);
    split2_kernel<<<(CP*CIN + 255)/256, 256>>>(Wg, Wgh, Wgl, Wz, Wzh, Wzl, CP*CIN);
    proj_mma  <<<dim3(32,3,4), 512, G_SMEM2>>>();
    logits_mma<<<dim3(32,4),   512, L_SMEM>>>();
    apply_mma <<<dim3(32,1,4), 512, G_SMEM>>>();
    z_mma     <<<dim3(32,2,4), 512, G_SMEM2>>>();
    bn_finalize_kernel<<<1, 256>>>();
    bn_apply_kernel<<<(B_*CIN*NS)/2048, 512>>>(x, gamma, beta, out);
}

// round 16
// speedup vs baseline: 1.0140x; 1.0140x over previous
#include <cuda_runtime.h>
#include <cuda_bf16.h>
#include <math.h>
#include <stdint.h>

#define B_   4
#define CIN  256
#define CP   128
#define NS   4096

__device__ float g_g[B_*CP*NS];
__device__ float g_z[B_*CIN*NS];
__device__ float g_bnsum[CIN];
__device__ float g_bnsq[CIN];
__device__ __nv_bfloat16 g_xh[B_*CIN*NS], g_xl[B_*CIN*NS];
__device__ __nv_bfloat16 g_Wth[CP*CIN], g_Wtl[CP*CIN];
__device__ __nv_bfloat16 g_Wph[CP*CIN], g_Wpl[CP*CIN];
__device__ __nv_bfloat16 g_Wgh[CP*CIN], g_Wgl[CP*CIN];
__device__ __nv_bfloat16 g_Wzh[CIN*CP], g_Wzl[CIN*CP];
__device__ __nv_bfloat16 g_th[B_*CP*NS], g_tl[B_*CP*NS];
__device__ __nv_bfloat16 g_ph[B_*CP*NS], g_pl[B_*CP*NS];
__device__ __nv_bfloat16 g_gh[B_*CP*NS], g_gl[B_*CP*NS];
__device__ __nv_bfloat16 g_yh[B_*CP*NS], g_yl[B_*CP*NS];
__device__ __nv_bfloat16 g_Eh[(size_t)B_*NS*NS], g_El[(size_t)B_*NS*NS];

// ---------------- helpers ----------------
__device__ __forceinline__ uint32_t smem_u32(const void* p) {
    uint32_t a;
    asm("{ .reg .u64 t; cvta.to.shared.u64 t, %1; cvt.u32.u64 %0, t; }" : "=r"(a) : "l"(p));
    return a;
}
#define CP16(dst, src) asm volatile("cp.async.cg.shared.global [%0], [%1], 16;" :: "r"(dst), "l"(src))
#define CPCOMMIT() asm volatile("cp.async.commit_group;" ::: "memory")
#define CPWAIT0() asm volatile("cp.async.wait_group 0;" ::: "memory")
#define CPWAIT1() asm volatile("cp.async.wait_group 1;" ::: "memory")
#define CPWAIT2() asm volatile("cp.async.wait_group 2;" ::: "memory")

__device__ __forceinline__ void ldm_x4_t(uint32_t* r, uint32_t addr) {
    asm volatile("ldmatrix.sync.aligned.m8n8.x4.trans.shared.b16 {%0,%1,%2,%3}, [%4];"
        : "=r"(r[0]), "=r"(r[1]), "=r"(r[2]), "=r"(r[3]) : "r"(addr));
}
__device__ __forceinline__ void ldm_x4(uint32_t* r, uint32_t addr) {
    asm volatile("ldmatrix.sync.aligned.m8n8.x4.shared.b16 {%0,%1,%2,%3}, [%4];"
        : "=r"(r[0]), "=r"(r[1]), "=r"(r[2]), "=r"(r[3]) : "r"(addr));
}
__device__ __forceinline__ void mma_bf16(float* c, const uint32_t* a, const uint32_t* b) {
    asm volatile("mma.sync.aligned.m16n8k16.row.col.f32.bf16.bf16.f32 "
        "{%0,%1,%2,%3}, {%4,%5,%6,%7}, {%8,%9}, {%0,%1,%2,%3};"
        : "+f"(c[0]), "+f"(c[1]), "+f"(c[2]), "+f"(c[3])
        : "r"(a[0]), "r"(a[1]), "r"(a[2]), "r"(a[3]), "r"(b[0]), "r"(b[1]));
}
__device__ __forceinline__ void split2(float a, float b, uint32_t& h, uint32_t& l) {
    __nv_bfloat16 ha = __float2bfloat16(a), hb = __float2bfloat16(b);
    h = (uint32_t)__bfloat16_as_ushort(ha) | ((uint32_t)__bfloat16_as_ushort(hb) << 16);
    __nv_bfloat16 la = __float2bfloat16(a - __bfloat162float(ha));
    __nv_bfloat16 lb = __float2bfloat16(b - __bfloat162float(hb));
    l = (uint32_t)__bfloat16_as_ushort(la) | ((uint32_t)__bfloat16_as_ushort(lb) << 16);
}

// ============================================================
// small kernels
// ============================================================
__global__ __launch_bounds__(256) void split_kernel(
    const float* __restrict__ src, __nv_bfloat16* __restrict__ h,
    __nv_bfloat16* __restrict__ l, int n)
{
    // fold-in: block 0 zeroes BN accumulators (runs long before z_mma)
    if (blockIdx.x == 0 && threadIdx.x < CIN) {
        g_bnsum[threadIdx.x] = 0.f;
        g_bnsq[threadIdx.x]  = 0.f;
    }
    int i = blockIdx.x*256 + threadIdx.x;
    if (i >= n) return;
    float v = src[i];
    __nv_bfloat16 hb = __float2bfloat16(v);
    h[i] = hb;
    l[i] = __float2bfloat16(v - __bfloat162float(hb));
}
__global__ __launch_bounds__(256) void split2_kernel(
    const float* __restrict__ s1, __nv_bfloat16* __restrict__ h1, __nv_bfloat16* __restrict__ l1,
    const float* __restrict__ s2, __nv_bfloat16* __restrict__ h2, __nv_bfloat16* __restrict__ l2,
    int n)
{
    int i = blockIdx.x*256 + threadIdx.x;
    if (i >= n) return;
    float v = s1[i];
    __nv_bfloat16 hb = __float2bfloat16(v);
    h1[i] = hb; l1[i] = __float2bfloat16(v - __bfloat162float(hb));
    v = s2[i];
    hb = __float2bfloat16(v);
    h2[i] = hb; l2[i] = __float2bfloat16(v - __bfloat162float(hb));
}

// ============================================================
// shared GEMM machinery: 128x128 CTA tile, 64-k chunks, 3-stage (R14)
// ============================================================
#define ATS 72
#define ATB 18432u
#define BTS 136
#define BTB 17408u
#define ABUF (2u*ATB + 2u*BTB)
#define G_SMEM (3u*ABUF)

__device__ __forceinline__ void stage_g(uint32_t buf,
    const __nv_bfloat16* Ah, const __nv_bfloat16* Al,
    const __nv_bfloat16* Bh, const __nv_bfloat16* Bl,
    int kc, int m0, int n0, int K, int tid)
{
    #pragma unroll
    for (int i = 0; i < 2; i++) {
        int idx = tid + i*512, row = idx>>3, ch = idx&7;
        uint32_t d = (uint32_t)(row*(ATS*2) + ch*16);
        size_t so = (size_t)(m0+row)*K + kc*64 + ch*8;
        CP16(buf + d,       Ah + so);
        CP16(buf + ATB + d, Al + so);
    }
    #pragma unroll
    for (int i = 0; i < 2; i++) {
        int idx = tid + i*512, row = idx>>4, ch = idx&15;
        uint32_t d = (uint32_t)(row*(BTS*2) + ch*16);
        size_t so = (size_t)(kc*64+row)*NS + n0 + ch*8;
        CP16(buf + 2u*ATB + d,       Bh + so);
        CP16(buf + 2u*ATB + BTB + d, Bl + so);
    }
}

__device__ __forceinline__ void gemm_loop(uint32_t sb,
    const __nv_bfloat16* pAh, const __nv_bfloat16* pAl,
    const __nv_bfloat16* pBh, const __nv_bfloat16* pBl,
    int m0, int n0, int K, int nk, int tid, int wid, int lane,
    float acc[2][4][4])
{
    #pragma unroll
    for (int s = 0; s < 3; s++) {
        if (s < nk) stage_g(sb + (uint32_t)s*ABUF, pAh, pAl, pBh, pBl, s, m0, n0, K, tid);
        CPCOMMIT();
    }
    const int wc = (wid&3)*32, wn = (wid>>2)*32;
    const uint32_t rowAa = (lane&15), colAa = (lane>>4)*8;
    const uint32_t rowB16 = (lane&15), colB8 = (lane>>4)*8;

    int sslot = 0;
    for (int kc = 0; kc < nk; kc++) {
        CPWAIT2();
        __syncthreads();
        const uint32_t buf = sb + (uint32_t)sslot*ABUF;
        #pragma unroll
        for (int k0 = 0; k0 < 64; k0 += 16) {
            uint32_t ah[2][4], al[2][4], bh[2][4], bl[2][4];
            #pragma unroll
            for (int ct = 0; ct < 2; ct++) {
                uint32_t ao = buf + ((wc + ct*16 + rowAa)*ATS + k0 + colAa)*2;
                ldm_x4(ah[ct], ao);
                ldm_x4(al[ct], ao + ATB);
            }
            #pragma unroll
            for (int j = 0; j < 2; j++) {
                uint32_t bo = buf + 2u*ATB + ((k0+rowB16)*BTS + wn + j*16 + colB8)*2;
                ldm_x4_t(bh[j], bo);
                ldm_x4_t(bl[j], bo + BTB);
            }
            #pragma unroll
            for (int ct = 0; ct < 2; ct++)
                #pragma unroll
                for (int nt = 0; nt < 4; nt++)
                    mma_bf16(acc[ct][nt], ah[ct], &bh[nt>>1][(nt&1)*2]);
            #pragma unroll
            for (int ct = 0; ct < 2; ct++)
                #pragma unroll
                for (int nt = 0; nt < 4; nt++)
                    mma_bf16(acc[ct][nt], ah[ct], &bl[nt>>1][(nt&1)*2]);
            #pragma unroll
            for (int ct = 0; ct < 2; ct++)
                #pragma unroll
                for (int nt = 0; nt < 4; nt++)
                    mma_bf16(acc[ct][nt], al[ct], &bh[nt>>1][(nt&1)*2]);
        }
        __syncthreads();
        if (kc + 3 < nk)
            stage_g(buf, pAh, pAl, pBh, pBl, kc+3, m0, n0, K, tid);
        CPCOMMIT();
        sslot = (sslot == 2) ? 0 : sslot + 1;
    }
}

__device__ __forceinline__ void epi_bf(__nv_bfloat16* ch, __nv_bfloat16* cl,
                                       float acc[2][4][4], int m0, int n0, int wid, int lane)
{
    const int wc = (wid&3)*32, wn = (wid>>2)*32;
    const int r0 = lane>>2, cb = (lane&3)*2;
    #pragma unroll
    for (int ct = 0; ct < 2; ct++) {
        const int cg = m0 + wc + ct*16 + r0;
        #pragma unroll
        for (int nt = 0; nt < 4; nt++) {
            const int ng = n0 + wn + nt*8 + cb;
            uint32_t h, l;
            split2(acc[ct][nt][0], acc[ct][nt][1], h, l);
            *(uint32_t*)(ch + (size_t)cg*NS + ng) = h;
            *(uint32_t*)(cl + (size_t)cg*NS + ng) = l;
            split2(acc[ct][nt][2], acc[ct][nt][3], h, l);
            *(uint32_t*)(ch + (size_t)(cg+8)*NS + ng) = h;
            *(uint32_t*)(cl + (size_t)(cg+8)*NS + ng) = l;
        }
    }
}
__device__ __forceinline__ void epi_f32(float* Cout, float acc[2][4][4],
                                        int m0, int n0, int wid, int lane)
{
    const int wc = (wid&3)*32, wn = (wid>>2)*32;
    const int r0 = lane>>2, cb = (lane&3)*2;
    #pragma unroll
    for (int ct = 0; ct < 2; ct++) {
        const int cg = m0 + wc + ct*16 + r0;
        #pragma unroll
        for (int nt = 0; nt < 4; nt++) {
            const int ng = n0 + wn + nt*8 + cb;
            *(float2*)(Cout + (size_t)cg*NS + ng)     = make_float2(acc[ct][nt][0], acc[ct][nt][1]);
            *(float2*)(Cout + (size_t)(cg+8)*NS + ng) = make_float2(acc[ct][nt][2], acc[ct][nt][3]);
        }
    }
}

// ============================================================
// proj: one launch for t/p/g. grid (32, 3, 4), 512 thr
// ============================================================
__global__ __launch_bounds__(512) void proj_mma()
{
    extern __shared__ char smem[];
    const int b = blockIdx.z, w = blockIdx.y, n0 = blockIdx.x*128;
    const int tid = threadIdx.x, wid = tid>>5, lane = tid&31;
    const uint32_t sb = smem_u32(smem);
    const __nv_bfloat16* Ah = (w == 0) ? g_Wth : (w == 1) ? g_Wph : g_Wgh;
    const __nv_bfloat16* Al = (w == 0) ? g_Wtl : (w == 1) ? g_Wpl : g_Wgl;
    const __nv_bfloat16* Bh = g_xh + (size_t)b*CIN*NS;
    const __nv_bfloat16* Bl = g_xl + (size_t)b*CIN*NS;

    float acc[2][4][4] = {};
    gemm_loop(sb, Ah, Al, Bh, Bl, 0, n0, CIN, CIN/64, tid, wid, lane, acc);

    if (w == 0)      epi_bf(g_th + (size_t)b*CP*NS, g_tl + (size_t)b*CP*NS, acc, 0, n0, wid, lane);
    else if (w == 1) epi_bf(g_ph + (size_t)b*CP*NS, g_pl + (size_t)b*CP*NS, acc, 0, n0, wid, lane);
    else             epi_f32(g_g + (size_t)b*CP*NS, acc, 0, n0, wid, lane);
}

// ============================================================
// apply: y = g'·E (mode 1). z: z = Wz·y + BN partial sums (mode 0).
// ============================================================
__global__ __launch_bounds__(512) void hgemm3p(
    const __nv_bfloat16* __restrict__ Ah, const __nv_bfloat16* __restrict__ Al, size_t sAb,
    const __nv_bfloat16* __restrict__ Bh, const __nv_bfloat16* __restrict__ Bl, size_t sBb,
    float* __restrict__ C, __nv_bfloat16* __restrict__ Ch, __nv_bfloat16* __restrict__ Cl,
    size_t sCb, int K, int mode)
{
    extern __shared__ char smem[];
    __shared__ float s_bn[256];
    const int b = blockIdx.z, m0 = blockIdx.y*128, n0 = blockIdx.x*128;
    const int tid = threadIdx.x, wid = tid>>5, lane = tid&31;
    const uint32_t sb = smem_u32(smem);

    if (mode == 0 && tid < 256) s_bn[tid] = 0.f;

    float acc[2][4][4] = {};
    gemm_loop(sb, Ah + (size_t)b*sAb, Al + (size_t)b*sAb,
              Bh + (size_t)b*sBb, Bl + (size_t)b*sBb,
              m0, n0, K, K>>6, tid, wid, lane, acc);

    if (mode == 1) {
        epi_bf(Ch + (size_t)b*sCb, Cl + (size_t)b*sCb, acc, m0, n0, wid, lane);
        return;
    }

    __syncthreads();
    const int wc = (wid&3)*32, wn = (wid>>2)*32;
    const int r0 = lane>>2, cb = (lane&3)*2;
    float* Cout = C + (size_t)b*sCb;
    #pragma unroll
    for (int ct = 0; ct < 2; ct++) {
        const int lc = wc + ct*16 + r0;
        const int cg = m0 + lc;
        float s0 = 0.f, q0 = 0.f, s1 = 0.f, q1 = 0.f;
        #pragma unroll
        for (int nt = 0; nt < 4; nt++) {
            const int ng = n0 + wn + nt*8 + cb;
            float z0 = acc[ct][nt][0], z1 = acc[ct][nt][1];
            float z2 = acc[ct][nt][2], z3 = acc[ct][nt][3];
            *(float2*)(Cout + (size_t)cg*NS + ng)     = make_float2(z0, z1);
            *(float2*)(Cout + (size_t)(cg+8)*NS + ng) = make_float2(z2, z3);
            s0 += z0 + z1; q0 += z0*z0 + z1*z1;
            s1 += z2 + z3; q1 += z2*z2 + z3*z3;
        }
        #pragma unroll
        for (int sh = 1; sh < 4; sh <<= 1) {
            s0 += __shfl_xor_sync(0xFFFFFFFF, s0, sh);
            q0 += __shfl_xor_sync(0xFFFFFFFF, q0, sh);
            s1 += __shfl_xor_sync(0xFFFFFFFF, s1, sh);
            q1 += __shfl_xor_sync(0xFFFFFFFF, q1, sh);
        }
        if ((lane&3) == 0) {
            atomicAdd(s_bn + lc, s0);        atomicAdd(s_bn + 128 + lc, q0);
            atomicAdd(s_bn + lc + 8, s1);    atomicAdd(s_bn + 128 + lc + 8, q1);
        }
    }
    __syncthreads();
    if (tid < 128) {
        atomicAdd(&g_bnsum[m0 + tid], s_bn[tid]);
        atomicAdd(&g_bnsq[m0 + tid],  s_bn[128 + tid]);
    }
}

// ============================================================
// logits (R14): s = p^T t; E=exp(s) hi/lo SMEM-staged coalesced;
// Linv + gscale fused. grid (32, 4), 512 thr
// ============================================================
#define LTS 136
#define LTB 34816u
#define L_SMEM (6u*LTB)

__device__ __forceinline__ void stage_pt(uint32_t dbase, const __nv_bfloat16* sh,
                                         const __nv_bfloat16* sl, int col0, int tid) {
    #pragma unroll
    for (int i = 0; i < 4; i++) {
        int idx = tid + i*512, row = idx>>4, ch = idx&15;
        uint32_t d = (uint32_t)(row*(LTS*2) + ch*16);
        CP16(dbase + d,       sh + (size_t)row*NS + col0 + ch*8);
        CP16(dbase + LTB + d, sl + (size_t)row*NS + col0 + ch*8);
    }
}

__global__ __launch_bounds__(512) void logits_mma()
{
    extern __shared__ char smem[];
    const int b = blockIdx.y, m0 = blockIdx.x*128;
    const int tid = threadIdx.x, wid = tid>>5, lane = tid&31;
    const uint32_t sb = smem_u32(smem);
    const __nv_bfloat16* th = g_th + (size_t)b*CP*NS;
    const __nv_bfloat16* tl = g_tl + (size_t)b*CP*NS;

    stage_pt(sb, g_ph + (size_t)b*CP*NS, g_pl + (size_t)b*CP*NS, m0, tid);
    stage_pt(sb + 2u*LTB, th, tl, 0, tid);     CPCOMMIT();
    stage_pt(sb + 4u*LTB, th, tl, 128, tid);   CPCOMMIT();

    const int mw = (wid&3)*32, nw = (wid>>2)*32;
    const uint32_t rowA = (lane&7) + ((lane>>4)<<3);
    const uint32_t colA = ((lane>>3)&1)*8;
    const uint32_t rowB16 = (lane&15), colB8 = (lane>>4)*8;
    const int r0 = lane>>2, cb = (lane&3)*2;

    float acc[2][4][4] = {};
    float rs[2][2] = {};

    for (int nc = 0; nc < 32; nc++) {
        if (nc >= 30) { CPWAIT0(); } else { CPWAIT1(); }
        __syncthreads();
        const uint32_t bufB = sb + 2u*LTB + (uint32_t)(nc&1)*(2u*LTB);
        #pragma unroll
        for (int k0 = 0; k0 < 128; k0 += 16) {
            uint32_t ah[2][4], al[2][4], bh[2][4], bl[2][4];
            #pragma unroll
            for (int mt = 0; mt < 2; mt++) {
                uint32_t ao = sb + ((k0+rowA)*LTS + mw + mt*16 + colA)*2;
                ldm_x4_t(ah[mt], ao);
                ldm_x4_t(al[mt], ao + LTB);
            }
            #pragma unroll
            for (int j = 0; j < 2; j++) {
                uint32_t bo = bufB + ((k0+rowB16)*LTS + nw + j*16 + colB8)*2;
                ldm_x4_t(bh[j], bo);
                ldm_x4_t(bl[j], bo + LTB);
            }
            #pragma unroll
            for (int mt = 0; mt < 2; mt++)
                #pragma unroll
                for (int nt = 0; nt < 4; nt++)
                    mma_bf16(acc[mt][nt], ah[mt], &bh[nt>>1][(nt&1)*2]);
            #pragma unroll
            for (int mt = 0; mt < 2; mt++)
                #pragma unroll
                for (int nt = 0; nt < 4; nt++)
                    mma_bf16(acc[mt][nt], ah[mt], &bl[nt>>1][(nt&1)*2]);
            #pragma unroll
            for (int mt = 0; mt < 2; mt++)
                #pragma unroll
                for (int nt = 0; nt < 4; nt++)
                    mma_bf16(acc[mt][nt], al[mt], &bh[nt>>1][(nt&1)*2]);
        }
        __syncthreads();

        #pragma unroll
        for (int mt = 0; mt < 2; mt++) {
            const int lr = mw + mt*16 + r0;
            #pragma unroll
            for (int nt = 0; nt < 4; nt++) {
                float e0 = __expf(acc[mt][nt][0]);
                float e1 = __expf(acc[mt][nt][1]);
                float e2 = __expf(acc[mt][nt][2]);
                float e3 = __expf(acc[mt][nt][3]);
                rs[mt][0] += e0 + e1;
                rs[mt][1] += e2 + e3;
                const int lc = nw + nt*8 + cb;
                uint32_t h, l;
                split2(e0, e1, h, l);
                *(uint32_t*)(smem + (bufB - sb) + (uint32_t)(lr*LTS + lc)*2)       = h;
                *(uint32_t*)(smem + (bufB - sb) + LTB + (uint32_t)(lr*LTS + lc)*2) = l;
                split2(e2, e3, h, l);
                *(uint32_t*)(smem + (bufB - sb) + (uint32_t)((lr+8)*LTS + lc)*2)       = h;
                *(uint32_t*)(smem + (bufB - sb) + LTB + (uint32_t)((lr+8)*LTS + lc)*2) = l;
                acc[mt][nt][0]=acc[mt][nt][1]=acc[mt][nt][2]=acc[mt][nt][3]=0.f;
            }
        }
        __syncthreads();
        {
            const char* sB = smem + (bufB - sb);
            #pragma unroll
            for (int i = 0; i < 4; i++) {
                int idx = tid + i*512, row = idx>>4, ch = idx&15;
                size_t go = ((size_t)b*NS + m0 + row)*NS + nc*128 + ch*8;
                *(uint4*)(g_Eh + go) = *(const uint4*)(sB + (uint32_t)(row*LTS)*2 + ch*16);
                *(uint4*)(g_El + go) = *(const uint4*)(sB + LTB + (uint32_t)(row*LTS)*2 + ch*16);
            }
        }
        __syncthreads();
        if (nc + 2 < 32) {
            stage_pt(bufB, th, tl, (nc+2)*128, tid);
            CPCOMMIT();
        }
    }

    #pragma unroll
    for (int mt = 0; mt < 2; mt++)
        #pragma unroll
        for (int h = 0; h < 2; h++) {
            rs[mt][h] += __shfl_xor_sync(0xFFFFFFFF, rs[mt][h], 1);
            rs[mt][h] += __shfl_xor_sync(0xFFFFFFFF, rs[mt][h], 2);
        }
    __syncthreads();
    float* red = (float*)smem;
    if ((lane&3) == 0) {
        #pragma unroll
        for (int mt = 0; mt < 2; mt++)
            #pragma unroll
            for (int h = 0; h < 2; h++)
                red[(wid>>2)*128 + mw + mt*16 + r0 + h*8] = rs[mt][h];
    }
    __syncthreads();
    float* linv = (float*)(smem + 2048);
    if (tid < 128)
        linv[tid] = 1.0f / (red[tid] + red[128+tid] + red[256+tid] + red[384+tid]);
    __syncthreads();

    {
        const int c = tid >> 2, ms = (tid & 3) * 32;
        const float* gp = g_g + ((size_t)b*CP + c)*NS + m0 + ms;
        __nv_bfloat16* ghp = g_gh + ((size_t)b*CP + c)*NS + m0 + ms;
        __nv_bfloat16* glp = g_gl + ((size_t)b*CP + c)*NS + m0 + ms;
        #pragma unroll
        for (int j = 0; j < 32; j += 4) {
            float4 v = *(const float4*)(gp + j);
            v.x *= linv[ms+j]; v.y *= linv[ms+j+1]; v.z *= linv[ms+j+2]; v.w *= linv[ms+j+3];
            uint32_t h0, l0, h1, l1;
            split2(v.x, v.y, h0, l0);
            split2(v.z, v.w, h1, l1);
            *(uint2*)(ghp + j) = make_uint2(h0, h1);
            *(uint2*)(glp + j) = make_uint2(l0, l1);
        }
    }
}

// ============================================================
// bn_apply: stats computed inline from sums; float4 vectorized
// ============================================================
__global__ __launch_bounds__(512) void bn_apply_kernel(
    const float* __restrict__ x, const float* __restrict__ gamma,
    const float* __restrict__ beta, float* __restrict__ out)
{
    size_t i4 = ((size_t)blockIdx.x*512 + threadIdx.x) * 4;
    int c = (int)((i4 / NS) % CIN);
    const float inv_n = 1.0f / (float)(B_*NS);
    float mean = g_bnsum[c] * inv_n;
    float var  = g_bnsq[c] * inv_n - mean*mean;
    float invstd = rsqrtf(var + 1e-5f);
    float ga = gamma[c], be = beta[c];
    float4 zv = *(const float4*)(g_z + i4);
    float4 xv = *(const float4*)(x + i4);
    float4 o;
    o.x = (zv.x - mean)*invstd*ga + be + xv.x;
    o.y = (zv.y - mean)*invstd*ga + be + xv.y;
    o.z = (zv.z - mean)*invstd*ga + be + xv.z;
    o.w = (zv.w - mean)*invstd*ga + be + xv.w;
    *(float4*)(out + i4) = o;
}

// ============================================================
extern "C" void kernel_launch(void* const* d_in, const int* in_sizes, int n_in,
                              void* d_out, int out_size)
{
    const float* x     = (const float*)d_in[0];
    const float* Wt    = (const float*)d_in[1];
    const float* Wp    = (const float*)d_in[2];
    const float* Wg    = (const float*)d_in[3];
    const float* Wz    = (const float*)d_in[4];
    const float* gamma = (const float*)d_in[5];
    const float* beta  = (const float*)d_in[6];
    float* out = (float*)d_out;

    cudaFuncSetAttribute(hgemm3p,    cudaFuncAttributeMaxDynamicSharedMemorySize, G_SMEM);
    cudaFuncSetAttribute(proj_mma,   cudaFuncAttributeMaxDynamicSharedMemorySize, G_SMEM);
    cudaFuncSetAttribute(logits_mma, cudaFuncAttributeMaxDynamicSharedMemorySize, L_SMEM);

    __nv_bfloat16 *xh, *xl, *Wth, *Wtl, *Wph, *Wpl, *Wgh, *Wgl, *Wzh, *Wzl;
    __nv_bfloat16 *gh, *gl, *yh, *yl, *Eh, *El;
    float *z;
    cudaGetSymbolAddress((void**)&xh, g_xh);   cudaGetSymbolAddress((void**)&xl, g_xl);
    cudaGetSymbolAddress((void**)&Wth, g_Wth); cudaGetSymbolAddress((void**)&Wtl, g_Wtl);
    cudaGetSymbolAddress((void**)&Wph, g_Wph); cudaGetSymbolAddress((void**)&Wpl, g_Wpl);
    cudaGetSymbolAddress((void**)&Wgh, g_Wgh); cudaGetSymbolAddress((void**)&Wgl, g_Wgl);
    cudaGetSymbolAddress((void**)&Wzh, g_Wzh); cudaGetSymbolAddress((void**)&Wzl, g_Wzl);
    cudaGetSymbolAddress((void**)&gh, g_gh);   cudaGetSymbolAddress((void**)&gl, g_gl);
    cudaGetSymbolAddress((void**)&yh, g_yh);   cudaGetSymbolAddress((void**)&yl, g_yl);
    cudaGetSymbolAddress((void**)&Eh, g_Eh);   cudaGetSymbolAddress((void**)&El, g_El);
    cudaGetSymbolAddress((void**)&z, g_z);

    split_kernel <<<(B_*CIN*NS + 255)/256, 256>>>(x, xh, xl, B_*CIN*NS);
    split2_kernel<<<(CP*CIN + 255)/256, 256>>>(Wt, Wth, Wtl, Wp, Wph, Wpl, CP*CIN);
    split2_kernel<<<(CP*CIN + 255)/256, 256>>>(Wg, Wgh, Wgl, Wz, Wzh, Wzl, CP*CIN);
    proj_mma  <<<dim3(32,3,4), 512, G_SMEM>>>();
    logits_mma<<<dim3(32,4),   512, L_SMEM>>>();
    hgemm3p<<<dim3(32,1,4), 512, G_SMEM>>>(gh, gl, (size_t)CP*NS, Eh, El, (size_t)NS*NS,
        nullptr, yh, yl, (size_t)CP*NS, NS, 1);                                 // apply
    hgemm3p<<<dim3(32,2,4), 512, G_SMEM>>>(Wzh, Wzl, 0, yh, yl, (size_t)CP*NS,
        z, nullptr, nullptr, (size_t)CIN*NS, CP, 0);                            // z + BN sums
    bn_apply_kernel<<<(B_*CIN*NS)/2048, 512>>>(x, gamma, beta, out);
}

// round 17
// speedup vs baseline: 1.0210x; 1.0069x over previous
#include <cuda_runtime.h>
#include <cuda_bf16.h>
#include <math.h>
#include <stdint.h>

#define B_   4
#define CIN  256
#define CP   128
#define NS   4096

__device__ float g_g[B_*CP*NS];
__device__ float g_z[B_*CIN*NS];
__device__ float g_bnsum[CIN];
__device__ float g_bnsq[CIN];
__device__ __nv_bfloat16 g_xh[B_*CIN*NS], g_xl[B_*CIN*NS];
__device__ __nv_bfloat16 g_Wth[CP*CIN], g_Wtl[CP*CIN];
__device__ __nv_bfloat16 g_Wph[CP*CIN], g_Wpl[CP*CIN];
__device__ __nv_bfloat16 g_Wgh[CP*CIN], g_Wgl[CP*CIN];
__device__ __nv_bfloat16 g_Wzh[CIN*CP], g_Wzl[CIN*CP];
__device__ __nv_bfloat16 g_th[B_*CP*NS], g_tl[B_*CP*NS];
__device__ __nv_bfloat16 g_ph[B_*CP*NS], g_pl[B_*CP*NS];
__device__ __nv_bfloat16 g_gh[B_*CP*NS], g_gl[B_*CP*NS];
__device__ __nv_bfloat16 g_yh[B_*CP*NS], g_yl[B_*CP*NS];
__device__ __nv_bfloat16 g_Eh[(size_t)B_*NS*NS], g_El[(size_t)B_*NS*NS];

// ---------------- helpers ----------------
__device__ __forceinline__ uint32_t smem_u32(const void* p) {
    uint32_t a;
    asm("{ .reg .u64 t; cvta.to.shared.u64 t, %1; cvt.u32.u64 %0, t; }" : "=r"(a) : "l"(p));
    return a;
}
#define CP16(dst, src) asm volatile("cp.async.cg.shared.global [%0], [%1], 16;" :: "r"(dst), "l"(src))
#define CPCOMMIT() asm volatile("cp.async.commit_group;" ::: "memory")
#define CPWAIT0() asm volatile("cp.async.wait_group 0;" ::: "memory")
#define CPWAIT1() asm volatile("cp.async.wait_group 1;" ::: "memory")
#define CPWAIT2() asm volatile("cp.async.wait_group 2;" ::: "memory")

__device__ __forceinline__ void ldm_x4_t(uint32_t* r, uint32_t addr) {
    asm volatile("ldmatrix.sync.aligned.m8n8.x4.trans.shared.b16 {%0,%1,%2,%3}, [%4];"
        : "=r"(r[0]), "=r"(r[1]), "=r"(r[2]), "=r"(r[3]) : "r"(addr));
}
__device__ __forceinline__ void ldm_x4(uint32_t* r, uint32_t addr) {
    asm volatile("ldmatrix.sync.aligned.m8n8.x4.shared.b16 {%0,%1,%2,%3}, [%4];"
        : "=r"(r[0]), "=r"(r[1]), "=r"(r[2]), "=r"(r[3]) : "r"(addr));
}
__device__ __forceinline__ void mma_bf16(float* c, const uint32_t* a, const uint32_t* b) {
    asm volatile("mma.sync.aligned.m16n8k16.row.col.f32.bf16.bf16.f32 "
        "{%0,%1,%2,%3}, {%4,%5,%6,%7}, {%8,%9}, {%0,%1,%2,%3};"
        : "+f"(c[0]), "+f"(c[1]), "+f"(c[2]), "+f"(c[3])
        : "r"(a[0]), "r"(a[1]), "r"(a[2]), "r"(a[3]), "r"(b[0]), "r"(b[1]));
}
__device__ __forceinline__ void split2(float a, float b, uint32_t& h, uint32_t& l) {
    __nv_bfloat16 ha = __float2bfloat16(a), hb = __float2bfloat16(b);
    h = (uint32_t)__bfloat16_as_ushort(ha) | ((uint32_t)__bfloat16_as_ushort(hb) << 16);
    __nv_bfloat16 la = __float2bfloat16(a - __bfloat162float(ha));
    __nv_bfloat16 lb = __float2bfloat16(b - __bfloat162float(hb));
    l = (uint32_t)__bfloat16_as_ushort(la) | ((uint32_t)__bfloat16_as_ushort(lb) << 16);
}

// ============================================================
// small kernels
// ============================================================
__global__ __launch_bounds__(256) void split_kernel(
    const float* __restrict__ src, __nv_bfloat16* __restrict__ h,
    __nv_bfloat16* __restrict__ l, int n)
{
    if (blockIdx.x == 0 && threadIdx.x < CIN) {
        g_bnsum[threadIdx.x] = 0.f;
        g_bnsq[threadIdx.x]  = 0.f;
    }
    int i = blockIdx.x*256 + threadIdx.x;
    if (i >= n) return;
    float v = src[i];
    __nv_bfloat16 hb = __float2bfloat16(v);
    h[i] = hb;
    l[i] = __float2bfloat16(v - __bfloat162float(hb));
}
// all four weight splits in one launch (each CP*CIN = 32768 elems)
__global__ __launch_bounds__(256) void splitW_kernel(
    const float* __restrict__ wt, const float* __restrict__ wp,
    const float* __restrict__ wg, const float* __restrict__ wz)
{
    int i = blockIdx.x*256 + threadIdx.x;
    if (i >= CP*CIN) return;
    float v; __nv_bfloat16 hb;
    v = wt[i]; hb = __float2bfloat16(v); g_Wth[i] = hb; g_Wtl[i] = __float2bfloat16(v - __bfloat162float(hb));
    v = wp[i]; hb = __float2bfloat16(v); g_Wph[i] = hb; g_Wpl[i] = __float2bfloat16(v - __bfloat162float(hb));
    v = wg[i]; hb = __float2bfloat16(v); g_Wgh[i] = hb; g_Wgl[i] = __float2bfloat16(v - __bfloat162float(hb));
    v = wz[i]; hb = __float2bfloat16(v); g_Wzh[i] = hb; g_Wzl[i] = __float2bfloat16(v - __bfloat162float(hb));
}

// ============================================================
// shared GEMM machinery (R14/R16): 128x128 tile, 64-k chunks, 3-stage
// ============================================================
#define ATS 72
#define ATB 18432u
#define BTS 136
#define BTB 17408u
#define ABUF (2u*ATB + 2u*BTB)
#define G_SMEM (3u*ABUF)

__device__ __forceinline__ void stage_g(uint32_t buf,
    const __nv_bfloat16* Ah, const __nv_bfloat16* Al,
    const __nv_bfloat16* Bh, const __nv_bfloat16* Bl,
    int kc, int m0, int n0, int K, int tid)
{
    #pragma unroll
    for (int i = 0; i < 2; i++) {
        int idx = tid + i*512, row = idx>>3, ch = idx&7;
        uint32_t d = (uint32_t)(row*(ATS*2) + ch*16);
        size_t so = (size_t)(m0+row)*K + kc*64 + ch*8;
        CP16(buf + d,       Ah + so);
        CP16(buf + ATB + d, Al + so);
    }
    #pragma unroll
    for (int i = 0; i < 2; i++) {
        int idx = tid + i*512, row = idx>>4, ch = idx&15;
        uint32_t d = (uint32_t)(row*(BTS*2) + ch*16);
        size_t so = (size_t)(kc*64+row)*NS + n0 + ch*8;
        CP16(buf + 2u*ATB + d,       Bh + so);
        CP16(buf + 2u*ATB + BTB + d, Bl + so);
    }
}

// one k0-step of the fused 3-pass MMA; A at aBuf (stride ATS), B at bBuf (stride BTS)
__device__ __forceinline__ void mma_step(uint32_t aBuf, uint32_t bBuf, int k0,
    int wc, int wn, uint32_t rowAa, uint32_t colAa, uint32_t rowB16, uint32_t colB8,
    float acc[2][4][4])
{
    uint32_t ah[2][4], al[2][4], bh[2][4], bl[2][4];
    #pragma unroll
    for (int ct = 0; ct < 2; ct++) {
        uint32_t ao = aBuf + ((wc + ct*16 + rowAa)*ATS + k0 + colAa)*2;
        ldm_x4(ah[ct], ao);
        ldm_x4(al[ct], ao + ATB);
    }
    #pragma unroll
    for (int j = 0; j < 2; j++) {
        uint32_t bo = bBuf + ((k0+rowB16)*BTS + wn + j*16 + colB8)*2;
        ldm_x4_t(bh[j], bo);
        ldm_x4_t(bl[j], bo + BTB);
    }
    #pragma unroll
    for (int ct = 0; ct < 2; ct++)
        #pragma unroll
        for (int nt = 0; nt < 4; nt++)
            mma_bf16(acc[ct][nt], ah[ct], &bh[nt>>1][(nt&1)*2]);
    #pragma unroll
    for (int ct = 0; ct < 2; ct++)
        #pragma unroll
        for (int nt = 0; nt < 4; nt++)
            mma_bf16(acc[ct][nt], ah[ct], &bl[nt>>1][(nt&1)*2]);
    #pragma unroll
    for (int ct = 0; ct < 2; ct++)
        #pragma unroll
        for (int nt = 0; nt < 4; nt++)
            mma_bf16(acc[ct][nt], al[ct], &bh[nt>>1][(nt&1)*2]);
}

__device__ __forceinline__ void gemm_loop(uint32_t sb,
    const __nv_bfloat16* pAh, const __nv_bfloat16* pAl,
    const __nv_bfloat16* pBh, const __nv_bfloat16* pBl,
    int m0, int n0, int K, int nk, int tid, int wid, int lane,
    float acc[2][4][4])
{
    #pragma unroll
    for (int s = 0; s < 3; s++) {
        if (s < nk) stage_g(sb + (uint32_t)s*ABUF, pAh, pAl, pBh, pBl, s, m0, n0, K, tid);
        CPCOMMIT();
    }
    const int wc = (wid&3)*32, wn = (wid>>2)*32;
    const uint32_t rowAa = (lane&15), colAa = (lane>>4)*8;
    const uint32_t rowB16 = (lane&15), colB8 = (lane>>4)*8;

    int sslot = 0;
    for (int kc = 0; kc < nk; kc++) {
        CPWAIT2();
        __syncthreads();
        const uint32_t buf = sb + (uint32_t)sslot*ABUF;
        #pragma unroll
        for (int k0 = 0; k0 < 64; k0 += 16)
            mma_step(buf, buf + 2u*ATB, k0, wc, wn, rowAa, colAa, rowB16, colB8, acc);
        __syncthreads();
        if (kc + 3 < nk)
            stage_g(buf, pAh, pAl, pBh, pBl, kc+3, m0, n0, K, tid);
        CPCOMMIT();
        sslot = (sslot == 2) ? 0 : sslot + 1;
    }
}

__device__ __forceinline__ void epi_bf(__nv_bfloat16* ch, __nv_bfloat16* cl,
                                       float acc[2][4][4], int m0, int n0, int wid, int lane)
{
    const int wc = (wid&3)*32, wn = (wid>>2)*32;
    const int r0 = lane>>2, cb = (lane&3)*2;
    #pragma unroll
    for (int ct = 0; ct < 2; ct++) {
        const int cg = m0 + wc + ct*16 + r0;
        #pragma unroll
        for (int nt = 0; nt < 4; nt++) {
            const int ng = n0 + wn + nt*8 + cb;
            uint32_t h, l;
            split2(acc[ct][nt][0], acc[ct][nt][1], h, l);
            *(uint32_t*)(ch + (size_t)cg*NS + ng) = h;
            *(uint32_t*)(cl + (size_t)cg*NS + ng) = l;
            split2(acc[ct][nt][2], acc[ct][nt][3], h, l);
            *(uint32_t*)(ch + (size_t)(cg+8)*NS + ng) = h;
            *(uint32_t*)(cl + (size_t)(cg+8)*NS + ng) = l;
        }
    }
}
__device__ __forceinline__ void epi_f32(float* Cout, float acc[2][4][4],
                                        int m0, int n0, int wid, int lane)
{
    const int wc = (wid&3)*32, wn = (wid>>2)*32;
    const int r0 = lane>>2, cb = (lane&3)*2;
    #pragma unroll
    for (int ct = 0; ct < 2; ct++) {
        const int cg = m0 + wc + ct*16 + r0;
        #pragma unroll
        for (int nt = 0; nt < 4; nt++) {
            const int ng = n0 + wn + nt*8 + cb;
            *(float2*)(Cout + (size_t)cg*NS + ng)     = make_float2(acc[ct][nt][0], acc[ct][nt][1]);
            *(float2*)(Cout + (size_t)(cg+8)*NS + ng) = make_float2(acc[ct][nt][2], acc[ct][nt][3]);
        }
    }
}

// ============================================================
// proj: ONE CTA per n-tile computes t,p,g — x staged once.
// grid (32, 4), 512 thr. smem: B full 4 chunks (139264) + 2 A slots (73728) = 212992
// ============================================================
#define PB_OFF 0u
#define PA_OFF 139264u
#define PA_SLOT 36864u
#define P_SMEM 212992u

__device__ __forceinline__ void stage_pa(uint32_t buf, const __nv_bfloat16* Ah,
                                         const __nv_bfloat16* Al, int kc, int tid) {
    #pragma unroll
    for (int i = 0; i < 2; i++) {
        int idx = tid + i*512, row = idx>>3, ch = idx&7;
        uint32_t d = (uint32_t)(row*(ATS*2) + ch*16);
        size_t so = (size_t)row*CIN + kc*64 + ch*8;
        CP16(buf + d,       Ah + so);
        CP16(buf + ATB + d, Al + so);
    }
}

__global__ __launch_bounds__(512) void proj_mma()
{
    extern __shared__ char smem[];
    const int b = blockIdx.y, n0 = blockIdx.x*128;
    const int tid = threadIdx.x, wid = tid>>5, lane = tid&31;
    const uint32_t sb = smem_u32(smem);
    const __nv_bfloat16* Bh = g_xh + (size_t)b*CIN*NS;
    const __nv_bfloat16* Bl = g_xl + (size_t)b*CIN*NS;
    const __nv_bfloat16* WH[3] = { g_Wth, g_Wph, g_Wgh };
    const __nv_bfloat16* WL[3] = { g_Wtl, g_Wpl, g_Wgl };

    // stage all 4 B (x) chunks once
    #pragma unroll
    for (int kc = 0; kc < 4; kc++) {
        #pragma unroll
        for (int i = 0; i < 2; i++) {
            int idx = tid + i*512, row = idx>>4, ch = idx&15;
            uint32_t d = (uint32_t)(row*(BTS*2) + ch*16);
            size_t so = (size_t)(kc*64+row)*NS + n0 + ch*8;
            CP16(sb + PB_OFF + (uint32_t)kc*(2u*BTB) + d,       Bh + so);
            CP16(sb + PB_OFF + (uint32_t)kc*(2u*BTB) + BTB + d, Bl + so);
        }
        CPCOMMIT();
    }
    stage_pa(sb + PA_OFF,            WH[0], WL[0], 0, tid); CPCOMMIT();
    stage_pa(sb + PA_OFF + PA_SLOT,  WH[0], WL[0], 1, tid); CPCOMMIT();

    const int wc = (wid&3)*32, wn = (wid>>2)*32;
    const uint32_t rowAa = (lane&15), colAa = (lane>>4)*8;
    const uint32_t rowB16 = (lane&15), colB8 = (lane>>4)*8;

    float acc[2][4][4] = {};
    for (int it = 0; it < 12; it++) {
        const int w = it >> 2, kc = it & 3;
        CPWAIT1();
        __syncthreads();
        const uint32_t aBuf = sb + PA_OFF + (uint32_t)(it&1)*PA_SLOT;
        const uint32_t bBuf = sb + PB_OFF + (uint32_t)kc*(2u*BTB);
        #pragma unroll
        for (int k0 = 0; k0 < 64; k0 += 16)
            mma_step(aBuf, bBuf, k0, wc, wn, rowAa, colAa, rowB16, colB8, acc);
        __syncthreads();
        if (it + 2 < 12) {
            const int w2 = (it+2) >> 2, kc2 = (it+2) & 3;
            stage_pa(aBuf, WH[w2], WL[w2], kc2, tid);
        }
        CPCOMMIT();
        if (kc == 3) {
            if (w == 0)      epi_bf(g_th + (size_t)b*CP*NS, g_tl + (size_t)b*CP*NS, acc, 0, n0, wid, lane);
            else if (w == 1) epi_bf(g_ph + (size_t)b*CP*NS, g_pl + (size_t)b*CP*NS, acc, 0, n0, wid, lane);
            else             epi_f32(g_g + (size_t)b*CP*NS, acc, 0, n0, wid, lane);
            #pragma unroll
            for (int ct = 0; ct < 2; ct++)
                #pragma unroll
                for (int nt = 0; nt < 4; nt++)
                    acc[ct][nt][0]=acc[ct][nt][1]=acc[ct][nt][2]=acc[ct][nt][3]=0.f;
        }
    }
}

// ============================================================
// apply (mode 1) / z + BN (mode 0) via generic kernel (R16)
// ============================================================
__global__ __launch_bounds__(512) void hgemm3p(
    const __nv_bfloat16* __restrict__ Ah, const __nv_bfloat16* __restrict__ Al, size_t sAb,
    const __nv_bfloat16* __restrict__ Bh, const __nv_bfloat16* __restrict__ Bl, size_t sBb,
    float* __restrict__ C, __nv_bfloat16* __restrict__ Ch, __nv_bfloat16* __restrict__ Cl,
    size_t sCb, int K, int mode)
{
    extern __shared__ char smem[];
    __shared__ float s_bn[256];
    const int b = blockIdx.z, m0 = blockIdx.y*128, n0 = blockIdx.x*128;
    const int tid = threadIdx.x, wid = tid>>5, lane = tid&31;
    const uint32_t sb = smem_u32(smem);

    if (mode == 0 && tid < 256) s_bn[tid] = 0.f;

    float acc[2][4][4] = {};
    gemm_loop(sb, Ah + (size_t)b*sAb, Al + (size_t)b*sAb,
              Bh + (size_t)b*sBb, Bl + (size_t)b*sBb,
              m0, n0, K, K>>6, tid, wid, lane, acc);

    if (mode == 1) {
        epi_bf(Ch + (size_t)b*sCb, Cl + (size_t)b*sCb, acc, m0, n0, wid, lane);
        return;
    }

    __syncthreads();
    const int wc = (wid&3)*32, wn = (wid>>2)*32;
    const int r0 = lane>>2, cb = (lane&3)*2;
    float* Cout = C + (size_t)b*sCb;
    #pragma unroll
    for (int ct = 0; ct < 2; ct++) {
        const int lc = wc + ct*16 + r0;
        const int cg = m0 + lc;
        float s0 = 0.f, q0 = 0.f, s1 = 0.f, q1 = 0.f;
        #pragma unroll
        for (int nt = 0; nt < 4; nt++) {
            const int ng = n0 + wn + nt*8 + cb;
            float z0 = acc[ct][nt][0], z1 = acc[ct][nt][1];
            float z2 = acc[ct][nt][2], z3 = acc[ct][nt][3];
            *(float2*)(Cout + (size_t)cg*NS + ng)     = make_float2(z0, z1);
            *(float2*)(Cout + (size_t)(cg+8)*NS + ng) = make_float2(z2, z3);
            s0 += z0 + z1; q0 += z0*z0 + z1*z1;
            s1 += z2 + z3; q1 += z2*z2 + z3*z3;
        }
        #pragma unroll
        for (int sh = 1; sh < 4; sh <<= 1) {
            s0 += __shfl_xor_sync(0xFFFFFFFF, s0, sh);
            q0 += __shfl_xor_sync(0xFFFFFFFF, q0, sh);
            s1 += __shfl_xor_sync(0xFFFFFFFF, s1, sh);
            q1 += __shfl_xor_sync(0xFFFFFFFF, q1, sh);
        }
        if ((lane&3) == 0) {
            atomicAdd(s_bn + lc, s0);        atomicAdd(s_bn + 128 + lc, q0);
            atomicAdd(s_bn + lc + 8, s1);    atomicAdd(s_bn + 128 + lc + 8, q1);
        }
    }
    __syncthreads();
    if (tid < 128) {
        atomicAdd(&g_bnsum[m0 + tid], s_bn[tid]);
        atomicAdd(&g_bnsq[m0 + tid],  s_bn[128 + tid]);
    }
}

// ============================================================
// logits (R14/R16)
// ============================================================
#define LTS 136
#define LTB 34816u
#define L_SMEM (6u*LTB)

__device__ __forceinline__ void stage_pt(uint32_t dbase, const __nv_bfloat16* sh,
                                         const __nv_bfloat16* sl, int col0, int tid) {
    #pragma unroll
    for (int i = 0; i < 4; i++) {
        int idx = tid + i*512, row = idx>>4, ch = idx&15;
        uint32_t d = (uint32_t)(row*(LTS*2) + ch*16);
        CP16(dbase + d,       sh + (size_t)row*NS + col0 + ch*8);
        CP16(dbase + LTB + d, sl + (size_t)row*NS + col0 + ch*8);
    }
}

__global__ __launch_bounds__(512) void logits_mma()
{
    extern __shared__ char smem[];
    const int b = blockIdx.y, m0 = blockIdx.x*128;
    const int tid = threadIdx.x, wid = tid>>5, lane = tid&31;
    const uint32_t sb = smem_u32(smem);
    const __nv_bfloat16* th = g_th + (size_t)b*CP*NS;
    const __nv_bfloat16* tl = g_tl + (size_t)b*CP*NS;

    stage_pt(sb, g_ph + (size_t)b*CP*NS, g_pl + (size_t)b*CP*NS, m0, tid);
    stage_pt(sb + 2u*LTB, th, tl, 0, tid);     CPCOMMIT();
    stage_pt(sb + 4u*LTB, th, tl, 128, tid);   CPCOMMIT();

    const int mw = (wid&3)*32, nw = (wid>>2)*32;
    const uint32_t rowA = (lane&7) + ((lane>>4)<<3);
    const uint32_t colA = ((lane>>3)&1)*8;
    const uint32_t rowB16 = (lane&15), colB8 = (lane>>4)*8;
    const int r0 = lane>>2, cb = (lane&3)*2;

    float acc[2][4][4] = {};
    float rs[2][2] = {};

    for (int nc = 0; nc < 32; nc++) {
        if (nc >= 30) { CPWAIT0(); } else { CPWAIT1(); }
        __syncthreads();
        const uint32_t bufB = sb + 2u*LTB + (uint32_t)(nc&1)*(2u*LTB);
        #pragma unroll
        for (int k0 = 0; k0 < 128; k0 += 16) {
            uint32_t ah[2][4], al[2][4], bh[2][4], bl[2][4];
            #pragma unroll
            for (int mt = 0; mt < 2; mt++) {
                uint32_t ao = sb + ((k0+rowA)*LTS + mw + mt*16 + colA)*2;
                ldm_x4_t(ah[mt], ao);
                ldm_x4_t(al[mt], ao + LTB);
            }
            #pragma unroll
            for (int j = 0; j < 2; j++) {
                uint32_t bo = bufB + ((k0+rowB16)*LTS + nw + j*16 + colB8)*2;
                ldm_x4_t(bh[j], bo);
                ldm_x4_t(bl[j], bo + LTB);
            }
            #pragma unroll
            for (int mt = 0; mt < 2; mt++)
                #pragma unroll
                for (int nt = 0; nt < 4; nt++)
                    mma_bf16(acc[mt][nt], ah[mt], &bh[nt>>1][(nt&1)*2]);
            #pragma unroll
            for (int mt = 0; mt < 2; mt++)
                #pragma unroll
                for (int nt = 0; nt < 4; nt++)
                    mma_bf16(acc[mt][nt], ah[mt], &bl[nt>>1][(nt&1)*2]);
            #pragma unroll
            for (int mt = 0; mt < 2; mt++)
                #pragma unroll
                for (int nt = 0; nt < 4; nt++)
                    mma_bf16(acc[mt][nt], al[mt], &bh[nt>>1][(nt&1)*2]);
        }
        __syncthreads();

        #pragma unroll
        for (int mt = 0; mt < 2; mt++) {
            const int lr = mw + mt*16 + r0;
            #pragma unroll
            for (int nt = 0; nt < 4; nt++) {
                float e0 = __expf(acc[mt][nt][0]);
                float e1 = __expf(acc[mt][nt][1]);
                float e2 = __expf(acc[mt][nt][2]);
                float e3 = __expf(acc[mt][nt][3]);
                rs[mt][0] += e0 + e1;
                rs[mt][1] += e2 + e3;
                const int lc = nw + nt*8 + cb;
                uint32_t h, l;
                split2(e0, e1, h, l);
                *(uint32_t*)(smem + (bufB - sb) + (uint32_t)(lr*LTS + lc)*2)       = h;
                *(uint32_t*)(smem + (bufB - sb) + LTB + (uint32_t)(lr*LTS + lc)*2) = l;
                split2(e2, e3, h, l);
                *(uint32_t*)(smem + (bufB - sb) + (uint32_t)((lr+8)*LTS + lc)*2)       = h;
                *(uint32_t*)(smem + (bufB - sb) + LTB + (uint32_t)((lr+8)*LTS + lc)*2) = l;
                acc[mt][nt][0]=acc[mt][nt][1]=acc[mt][nt][2]=acc[mt][nt][3]=0.f;
            }
        }
        __syncthreads();
        {
            const char* sB = smem + (bufB - sb);
            #pragma unroll
            for (int i = 0; i < 4; i++) {
                int idx = tid + i*512, row = idx>>4, ch = idx&15;
                size_t go = ((size_t)b*NS + m0 + row)*NS + nc*128 + ch*8;
                *(uint4*)(g_Eh + go) = *(const uint4*)(sB + (uint32_t)(row*LTS)*2 + ch*16);
                *(uint4*)(g_El + go) = *(const uint4*)(sB + LTB + (uint32_t)(row*LTS)*2 + ch*16);
            }
        }
        __syncthreads();
        if (nc + 2 < 32) {
            stage_pt(bufB, th, tl, (nc+2)*128, tid);
            CPCOMMIT();
        }
    }

    #pragma unroll
    for (int mt = 0; mt < 2; mt++)
        #pragma unroll
        for (int h = 0; h < 2; h++) {
            rs[mt][h] += __shfl_xor_sync(0xFFFFFFFF, rs[mt][h], 1);
            rs[mt][h] += __shfl_xor_sync(0xFFFFFFFF, rs[mt][h], 2);
        }
    __syncthreads();
    float* red = (float*)smem;
    if ((lane&3) == 0) {
        #pragma unroll
        for (int mt = 0; mt < 2; mt++)
            #pragma unroll
            for (int h = 0; h < 2; h++)
                red[(wid>>2)*128 + mw + mt*16 + r0 + h*8] = rs[mt][h];
    }
    __syncthreads();
    float* linv = (float*)(smem + 2048);
    if (tid < 128)
        linv[tid] = 1.0f / (red[tid] + red[128+tid] + red[256+tid] + red[384+tid]);
    __syncthreads();

    {
        const int c = tid >> 2, ms = (tid & 3) * 32;
        const float* gp = g_g + ((size_t)b*CP + c)*NS + m0 + ms;
        __nv_bfloat16* ghp = g_gh + ((size_t)b*CP + c)*NS + m0 + ms;
        __nv_bfloat16* glp = g_gl + ((size_t)b*CP + c)*NS + m0 + ms;
        #pragma unroll
        for (int j = 0; j < 32; j += 4) {
            float4 v = *(const float4*)(gp + j);
            v.x *= linv[ms+j]; v.y *= linv[ms+j+1]; v.z *= linv[ms+j+2]; v.w *= linv[ms+j+3];
            uint32_t h0, l0, h1, l1;
            split2(v.x, v.y, h0, l0);
            split2(v.z, v.w, h1, l1);
            *(uint2*)(ghp + j) = make_uint2(h0, h1);
            *(uint2*)(glp + j) = make_uint2(l0, l1);
        }
    }
}

// ============================================================
// bn_apply (R16)
// ============================================================
__global__ __launch_bounds__(512) void bn_apply_kernel(
    const float* __restrict__ x, const float* __restrict__ gamma,
    const float* __restrict__ beta, float* __restrict__ out)
{
    size_t i4 = ((size_t)blockIdx.x*512 + threadIdx.x) * 4;
    int c = (int)((i4 / NS) % CIN);
    const float inv_n = 1.0f / (float)(B_*NS);
    float mean = g_bnsum[c] * inv_n;
    float var  = g_bnsq[c] * inv_n - mean*mean;
    float invstd = rsqrtf(var + 1e-5f);
    float ga = gamma[c], be = beta[c];
    float4 zv = *(const float4*)(g_z + i4);
    float4 xv = *(const float4*)(x + i4);
    float4 o;
    o.x = (zv.x - mean)*invstd*ga + be + xv.x;
    o.y = (zv.y - mean)*invstd*ga + be + xv.y;
    o.z = (zv.z - mean)*invstd*ga + be + xv.z;
    o.w = (zv.w - mean)*invstd*ga + be + xv.w;
    *(float4*)(out + i4) = o;
}

// ============================================================
extern "C" void kernel_launch(void* const* d_in, const int* in_sizes, int n_in,
                              void* d_out, int out_size)
{
    const float* x     = (const float*)d_in[0];
    const float* Wt    = (const float*)d_in[1];
    const float* Wp    = (const float*)d_in[2];
    const float* Wg    = (const float*)d_in[3];
    const float* Wz    = (const float*)d_in[4];
    const float* gamma = (const float*)d_in[5];
    const float* beta  = (const float*)d_in[6];
    float* out = (float*)d_out;

    cudaFuncSetAttribute(hgemm3p,    cudaFuncAttributeMaxDynamicSharedMemorySize, G_SMEM);
    cudaFuncSetAttribute(proj_mma,   cudaFuncAttributeMaxDynamicSharedMemorySize, P_SMEM);
    cudaFuncSetAttribute(logits_mma, cudaFuncAttributeMaxDynamicSharedMemorySize, L_SMEM);

    __nv_bfloat16 *xh, *xl, *Wzh, *Wzl;
    __nv_bfloat16 *gh, *gl, *yh, *yl, *Eh, *El;
    float *z;
    cudaGetSymbolAddress((void**)&xh, g_xh);   cudaGetSymbolAddress((void**)&xl, g_xl);
    cudaGetSymbolAddress((void**)&Wzh, g_Wzh); cudaGetSymbolAddress((void**)&Wzl, g_Wzl);
    cudaGetSymbolAddress((void**)&gh, g_gh);   cudaGetSymbolAddress((void**)&gl, g_gl);
    cudaGetSymbolAddress((void**)&yh, g_yh);   cudaGetSymbolAddress((void**)&yl, g_yl);
    cudaGetSymbolAddress((void**)&Eh, g_Eh);   cudaGetSymbolAddress((void**)&El, g_El);
    cudaGetSymbolAddress((void**)&z, g_z);

    split_kernel<<<(B_*CIN*NS + 255)/256, 256>>>(x, xh, xl, B_*CIN*NS);
    splitW_kernel<<<(CP*CIN + 255)/256, 256>>>(Wt, Wp, Wg, Wz);
    proj_mma  <<<dim3(32,4), 512, P_SMEM>>>();
    logits_mma<<<dim3(32,4), 512, L_SMEM>>>();
    hgemm3p<<<dim3(32,1,4), 512, G_SMEM>>>(gh, gl, (size_t)CP*NS, Eh, El, (size_t)NS*NS,
        nullptr, yh, yl, (size_t)CP*NS, NS, 1);                                 // apply
    hgemm3p<<<dim3(32,2,4), 512, G_SMEM>>>(Wzh, Wzl, 0, yh, yl, (size_t)CP*NS,
        z, nullptr, nullptr, (size_t)CIN*NS, CP, 0);                            // z + BN sums
    bn_apply_kernel<<<(B_*CIN*NS)/2048, 512>>>(x, gamma, beta, out);
}